// round 1
// baseline (speedup 1.0000x reference)
#include <cuda_runtime.h>
#include <cuda_bf16.h>

// ---------------------------------------------------------------------------
// YOLO loss reduction: 1024 x 28 x 28 cells, B=2 boxes, 20 classes -> 5 scalars
// (total, reg_l, cobj_l, nbj_l, cls_l)
// ---------------------------------------------------------------------------

#define NCELLS   802816      // 1024*28*28
#define NBLOCKS  3136        // NCELLS / 256
#define S_F      28.0f
#define N_BATCH  1024.0

__device__ double       g_acc[4];   // cls, nbj, reg, cobj raw sums
__device__ unsigned int g_flag;     // mask dtype: bit0 = float32, bit1 = packed uint8, else int32

// ---- kernel 0: reset accumulators (graph replay must be deterministic) ----
__global__ void yolo_init_k() {
    if (threadIdx.x < 4) g_acc[threadIdx.x] = 0.0;
    if (threadIdx.x == 0) g_flag = 0u;
}

// ---- kernel 1: detect the storage dtype of has_object_map -----------------
// Reads the first NCELLS/4 32-bit words (safe for u8/i32/f32 storage).
//  - word == 0x3f800000            -> float32 "1.0" present
//  - word > 1 && bytes all in {0,1} -> byte-packed bools present
__global__ void yolo_detect_k(const unsigned int* __restrict__ m) {
    unsigned int i = blockIdx.x * blockDim.x + threadIdx.x;
    unsigned int w = m[i];
    int isF = (w == 0x3f800000u);
    int isP = (w > 1u) && ((w & 0xFEFEFEFEu) == 0u);
    int bf = __syncthreads_or(isF);
    int bp = __syncthreads_or(isP);
    if (threadIdx.x == 0) {
        unsigned int f = (bf ? 1u : 0u) | (bp ? 2u : 0u);
        if (f) atomicOr(&g_flag, f);
    }
}

// ---- kernel 2: main reduction ---------------------------------------------
__global__ void __launch_bounds__(256) yolo_main_k(
    const float* __restrict__ pred,   // [NCELLS, 30]
    const float* __restrict__ tbox,   // [NCELLS, 4]
    const float* __restrict__ tcls,   // [NCELLS, 20]
    const void*  __restrict__ maskp)  // [NCELLS] (dtype per g_flag)
{
    __shared__ __align__(16) float sp[256 * 30];   // staged pred tile
    __shared__ __align__(16) float sb[256 * 4];    // staged target boxes
    __shared__ float smk[256];                     // mask as float
    __shared__ float red[8][4];

    const int tid   = threadIdx.x;
    const int cell0 = blockIdx.x * 256;

    // --- coalesced float4 staging of pred (7680 floats = 1920 float4) ---
    {
        const float4* p4  = (const float4*)(pred + (size_t)cell0 * 30);
        float4*       sp4 = (float4*)sp;
        #pragma unroll
        for (int i = tid; i < 1920; i += 256) sp4[i] = p4[i];
    }
    // --- target boxes (1024 floats = 256 float4) ---
    ((float4*)sb)[tid] = ((const float4*)(tbox + (size_t)cell0 * 4))[tid];
    // --- mask ---
    {
        unsigned int flag = g_flag;
        float mv;
        if (flag & 1u)      mv = ((const float*)maskp)[cell0 + tid];
        else if (flag & 2u) mv = (float)((const unsigned char*)maskp)[cell0 + tid];
        else                mv = (float)((const int*)maskp)[cell0 + tid];
        smk[tid] = mv;
    }
    __syncthreads();

    // --- class loss: streamed coalesced tcls reads vs shared pred ---
    float acc_cls = 0.0f;
    {
        const float* tcg = tcls + (size_t)cell0 * 20;
        #pragma unroll 4
        for (int e = tid; e < 256 * 20; e += 256) {
            int cl = e / 20;
            int ch = e - cl * 20;
            float d = sp[cl * 30 + 10 + ch] - tcg[e];
            acc_cls += smk[cl] * d * d;
        }
    }

    // --- per-cell box terms ---
    const float* p  = sp + tid * 30;
    const float* tb = sb + tid * 4;
    const float  m  = smk[tid];

    // target box xyxy
    float tcx = tb[0] / S_F, tcy = tb[1] / S_F;
    float thw = 0.5f * tb[2], thh = 0.5f * tb[3];
    float tbx1 = tcx - thw, tby1 = tcy - thh, tbx2 = tcx + thw, tby2 = tcy + thh;
    float ta = (tbx2 - tbx1) * (tby2 - tby1);

    float bx1[2], by1[2], bx2[2], by2[2], iou[2], cf[2];
    #pragma unroll
    for (int b = 0; b < 2; b++) {
        float x = p[5 * b + 0], y = p[5 * b + 1];
        float w = p[5 * b + 2], h = p[5 * b + 3];
        cf[b] = p[5 * b + 4];
        float cx = x / S_F, cy = y / S_F;
        float hw = 0.5f * w, hh = 0.5f * h;
        bx1[b] = cx - hw; by1[b] = cy - hh;
        bx2[b] = cx + hw; by2[b] = cy + hh;
        float ltx = fmaxf(bx1[b], tbx1), lty = fmaxf(by1[b], tby1);
        float rbx = fminf(bx2[b], tbx2), rby = fminf(by2[b], tby2);
        float wi = fmaxf(rbx - ltx, 0.0f), hi = fmaxf(rby - lty, 0.0f);
        float inter = wi * hi;
        float a1 = (bx2[b] - bx1[b]) * (by2[b] - by1[b]);
        iou[b] = inter / (a1 + ta - inter);
    }

    // argmax (first max wins on tie, matching jnp.argmax)
    int best = (iou[1] > iou[0]) ? 1 : 0;
    float biou = iou[best];
    float bbx1 = bx1[best], bby1 = by1[best], bbx2 = bx2[best], bby2 = by2[best];
    float bconf = cf[best];
    if (!(biou > 0.0f)) {
        bbx1 = bby1 = bbx2 = bby2 = 0.0f;
        bconf = 0.0f; biou = 0.0f;
    }

    float dx = bbx1 - tbx1, dy = bby1 - tby1;
    float lxy = dx * dx + dy * dy;
    float s1 = (bbx2 > 0.0f) ? sqrtf(bbx2) : 0.0f;
    float s2 = (bby2 > 0.0f) ? sqrtf(bby2) : 0.0f;
    float t1 = (tbx2 > 0.0f) ? sqrtf(tbx2) : 0.0f;
    float t2 = (tby2 > 0.0f) ? sqrtf(tby2) : 0.0f;
    float dw = s1 - t1, dh = s2 - t2;
    float lwh = dw * dw + dh * dh;

    float acc_reg  = m * (lxy + lwh);
    float dc       = bconf - biou;
    float acc_cobj = m * dc * dc;
    float acc_nbj  = (1.0f - m) * (cf[0] * cf[0] + cf[1] * cf[1]);

    // --- hierarchical reduction: warp shuffle -> shared -> double atomics ---
    float a4[4] = { acc_cls, acc_nbj, acc_reg, acc_cobj };
    #pragma unroll
    for (int j = 0; j < 4; j++) {
        #pragma unroll
        for (int o = 16; o; o >>= 1)
            a4[j] += __shfl_down_sync(0xffffffffu, a4[j], o);
    }
    int warp = tid >> 5, lane = tid & 31;
    if (lane == 0) {
        red[warp][0] = a4[0]; red[warp][1] = a4[1];
        red[warp][2] = a4[2]; red[warp][3] = a4[3];
    }
    __syncthreads();
    if (tid == 0) {
        double s[4] = {0.0, 0.0, 0.0, 0.0};
        #pragma unroll
        for (int w = 0; w < 8; w++)
            for (int j = 0; j < 4; j++) s[j] += (double)red[w][j];
        atomicAdd(&g_acc[0], s[0]);
        atomicAdd(&g_acc[1], s[1]);
        atomicAdd(&g_acc[2], s[2]);
        atomicAdd(&g_acc[3], s[3]);
    }
}

// ---- kernel 3: finalize ----------------------------------------------------
__global__ void yolo_fin_k(float* __restrict__ out) {
    double cls  = g_acc[0], nbj = g_acc[1], reg = g_acc[2], cobj = g_acc[3];
    double cls_l  = 2.0 * cls / N_BATCH;
    double nbj_l  = 0.5 * nbj / N_BATCH;
    double reg_l  = 5.0 * reg / N_BATCH;
    double cobj_l = cobj / N_BATCH;
    out[0] = (float)(cls_l + nbj_l + reg_l + cobj_l);
    out[1] = (float)reg_l;
    out[2] = (float)cobj_l;
    out[3] = (float)nbj_l;
    out[4] = (float)cls_l;
}

extern "C" void kernel_launch(void* const* d_in, const int* in_sizes, int n_in,
                              void* d_out, int out_size) {
    const float* pred = nullptr;
    const float* tbox = nullptr;
    const float* tcls = nullptr;
    const void*  mask = nullptr;
    // identify inputs by element count (robust to metadata ordering)
    for (int i = 0; i < n_in; i++) {
        switch (in_sizes[i]) {
            case 24084480: pred = (const float*)d_in[i]; break;  // NCELLS*30
            case 16056320: tcls = (const float*)d_in[i]; break;  // NCELLS*20
            case 3211264:  tbox = (const float*)d_in[i]; break;  // NCELLS*4
            case 802816:   mask = d_in[i];               break;  // NCELLS
        }
    }
    yolo_init_k<<<1, 32>>>();
    yolo_detect_k<<<NCELLS / 4 / 256, 256>>>((const unsigned int*)mask);
    yolo_main_k<<<NBLOCKS, 256>>>(pred, tbox, tcls, mask);
    yolo_fin_k<<<1, 1>>>((float*)d_out);
}

// round 2
// speedup vs baseline: 1.5758x; 1.5758x over previous
#include <cuda_runtime.h>
#include <cuda_bf16.h>

// ---------------------------------------------------------------------------
// YOLO loss reduction: 1024 x 28 x 28 cells, B=2 boxes, 20 classes -> 5 scalars
// (total, reg_l, cobj_l, nbj_l, cls_l)
// Two launches: [init+dtype-detect]  ->  [main reduction + last-block finalize]
// ---------------------------------------------------------------------------

#define NCELLS   802816      // 1024*28*28
#define NBLOCKS  3136        // NCELLS / 256
#define INV_S    0.0357142857142857f   // 1/28
#define N_BATCH  1024.0

__device__ double       g_acc[4];   // cls, nbj, reg, cobj raw sums
__device__ unsigned int g_flag;     // mask dtype: bit0 = float32, bit1 = packed uint8, else int32
__device__ unsigned int g_count;    // finished-block ticket

// ---- kernel A: reset accumulators + detect mask dtype (1 block) -----------
// Scans the first 2048 32-bit words of the mask buffer (8 KB, valid for any
// candidate dtype).  word == 0x3f800000 -> float32;  word with all bytes in
// {0,1} and value > 1 -> byte-packed bool/uint8;  otherwise int32 fallback.
__global__ void yolo_init_detect_k(const unsigned int* __restrict__ m) {
    int isF = 0, isP = 0;
    #pragma unroll
    for (int j = 0; j < 8; j++) {
        unsigned int w = m[threadIdx.x + 256 * j];
        isF |= (w == 0x3f800000u);
        isP |= (w > 1u) && ((w & 0xFEFEFEFEu) == 0u);
    }
    int bf = __syncthreads_or(isF);
    int bp = __syncthreads_or(isP);
    if (threadIdx.x == 0) {
        g_flag  = (bf ? 1u : 0u) | (bp ? 2u : 0u);
        g_count = 0u;
    }
    if (threadIdx.x < 4) g_acc[threadIdx.x] = 0.0;
}

// ---- kernel B: main reduction + last-block finalize ------------------------
__global__ void __launch_bounds__(256) yolo_main_k(
    const float* __restrict__ pred,   // [NCELLS, 30]
    const float* __restrict__ tbox,   // [NCELLS, 4]
    const float* __restrict__ tcls,   // [NCELLS, 20]
    const void*  __restrict__ maskp,  // [NCELLS] (dtype per g_flag)
    float*       __restrict__ out)
{
    __shared__ __align__(16) float sp[256 * 30];   // staged pred tile
    __shared__ __align__(16) float sb[256 * 4];    // staged target boxes
    __shared__ float smk[256];                     // mask as float
    __shared__ float red[8][4];

    const int tid   = threadIdx.x;
    const int cell0 = blockIdx.x * 256;

    // --- coalesced float4 staging of pred (7680 floats = 1920 float4) ---
    {
        const float4* p4  = (const float4*)(pred + (size_t)cell0 * 30);
        float4*       sp4 = (float4*)sp;
        #pragma unroll
        for (int i = tid; i < 1920; i += 256) sp4[i] = p4[i];
    }
    // --- target boxes (1024 floats = 256 float4) ---
    ((float4*)sb)[tid] = ((const float4*)(tbox + (size_t)cell0 * 4))[tid];
    // --- mask ---
    {
        unsigned int flag = g_flag;
        float mv;
        if (flag & 1u)      mv = ((const float*)maskp)[cell0 + tid];
        else if (flag & 2u) mv = (float)((const unsigned char*)maskp)[cell0 + tid];
        else                mv = (float)((const int*)maskp)[cell0 + tid];
        smk[tid] = mv;
    }
    __syncthreads();

    // --- class loss: vectorized streamed tcls reads vs shared pred ---
    // 256 cells * 20 ch = 5120 floats = 1280 float4.  20 % 4 == 0, so one
    // float4 never crosses a cell boundary: cl = e4/5, ch = 4*(e4%5).
    float acc_cls = 0.0f;
    {
        const float4* tcg4 = (const float4*)(tcls + (size_t)cell0 * 20);
        #pragma unroll
        for (int j = 0; j < 5; j++) {
            int e4 = tid + 256 * j;
            int cl = e4 / 5;
            int ch = 4 * (e4 - cl * 5);
            float4 t  = tcg4[e4];
            const float* pc = sp + cl * 30 + 10 + ch;
            float mm = smk[cl];
            float d0 = pc[0] - t.x;
            float d1 = pc[1] - t.y;
            float d2 = pc[2] - t.z;
            float d3 = pc[3] - t.w;
            acc_cls += mm * (d0 * d0 + d1 * d1 + d2 * d2 + d3 * d3);
        }
    }

    // --- per-cell box terms ---
    const float* p  = sp + tid * 30;
    const float* tb = sb + tid * 4;
    const float  m  = smk[tid];

    // target box xyxy
    float tcx = tb[0] * INV_S, tcy = tb[1] * INV_S;
    float thw = 0.5f * tb[2], thh = 0.5f * tb[3];
    float tbx1 = tcx - thw, tby1 = tcy - thh, tbx2 = tcx + thw, tby2 = tcy + thh;
    float ta = (tbx2 - tbx1) * (tby2 - tby1);

    float bx1[2], by1[2], bx2[2], by2[2], iou[2], cf[2];
    #pragma unroll
    for (int b = 0; b < 2; b++) {
        float x = p[5 * b + 0], y = p[5 * b + 1];
        float w = p[5 * b + 2], h = p[5 * b + 3];
        cf[b] = p[5 * b + 4];
        float cx = x * INV_S, cy = y * INV_S;
        float hw = 0.5f * w, hh = 0.5f * h;
        bx1[b] = cx - hw; by1[b] = cy - hh;
        bx2[b] = cx + hw; by2[b] = cy + hh;
        float ltx = fmaxf(bx1[b], tbx1), lty = fmaxf(by1[b], tby1);
        float rbx = fminf(bx2[b], tbx2), rby = fminf(by2[b], tby2);
        float wi = fmaxf(rbx - ltx, 0.0f), hi = fmaxf(rby - lty, 0.0f);
        float inter = wi * hi;
        float a1 = (bx2[b] - bx1[b]) * (by2[b] - by1[b]);
        iou[b] = inter / (a1 + ta - inter);
    }

    // argmax (first max wins on tie, matching jnp.argmax)
    int best = (iou[1] > iou[0]) ? 1 : 0;
    float biou = iou[best];
    float bbx1 = bx1[best], bby1 = by1[best], bbx2 = bx2[best], bby2 = by2[best];
    float bconf = cf[best];
    if (!(biou > 0.0f)) {
        bbx1 = bby1 = bbx2 = bby2 = 0.0f;
        bconf = 0.0f; biou = 0.0f;
    }

    float dx = bbx1 - tbx1, dy = bby1 - tby1;
    float lxy = dx * dx + dy * dy;
    float s1 = (bbx2 > 0.0f) ? sqrtf(bbx2) : 0.0f;
    float s2 = (bby2 > 0.0f) ? sqrtf(bby2) : 0.0f;
    float t1 = (tbx2 > 0.0f) ? sqrtf(tbx2) : 0.0f;
    float t2 = (tby2 > 0.0f) ? sqrtf(tby2) : 0.0f;
    float dw = s1 - t1, dh = s2 - t2;
    float lwh = dw * dw + dh * dh;

    float acc_reg  = m * (lxy + lwh);
    float dc       = bconf - biou;
    float acc_cobj = m * dc * dc;
    float acc_nbj  = (1.0f - m) * (cf[0] * cf[0] + cf[1] * cf[1]);

    // --- hierarchical reduction: warp shuffle -> shared -> double atomics ---
    float a4[4] = { acc_cls, acc_nbj, acc_reg, acc_cobj };
    #pragma unroll
    for (int j = 0; j < 4; j++) {
        #pragma unroll
        for (int o = 16; o; o >>= 1)
            a4[j] += __shfl_down_sync(0xffffffffu, a4[j], o);
    }
    int warp = tid >> 5, lane = tid & 31;
    if (lane == 0) {
        red[warp][0] = a4[0]; red[warp][1] = a4[1];
        red[warp][2] = a4[2]; red[warp][3] = a4[3];
    }
    __syncthreads();
    if (tid == 0) {
        double s[4] = {0.0, 0.0, 0.0, 0.0};
        #pragma unroll
        for (int w = 0; w < 8; w++)
            for (int j = 0; j < 4; j++) s[j] += (double)red[w][j];
        atomicAdd(&g_acc[0], s[0]);
        atomicAdd(&g_acc[1], s[1]);
        atomicAdd(&g_acc[2], s[2]);
        atomicAdd(&g_acc[3], s[3]);

        // last-block finalize (replaces the dedicated 1-thread kernel)
        __threadfence();
        unsigned int ticket = atomicAdd(&g_count, 1u);
        if (ticket == NBLOCKS - 1) {
            double cls  = atomicAdd(&g_acc[0], 0.0);
            double nbj  = atomicAdd(&g_acc[1], 0.0);
            double reg  = atomicAdd(&g_acc[2], 0.0);
            double cobj = atomicAdd(&g_acc[3], 0.0);
            double cls_l  = 2.0 * cls / N_BATCH;
            double nbj_l  = 0.5 * nbj / N_BATCH;
            double reg_l  = 5.0 * reg / N_BATCH;
            double cobj_l = cobj / N_BATCH;
            out[0] = (float)(cls_l + nbj_l + reg_l + cobj_l);
            out[1] = (float)reg_l;
            out[2] = (float)cobj_l;
            out[3] = (float)nbj_l;
            out[4] = (float)cls_l;
        }
    }
}

extern "C" void kernel_launch(void* const* d_in, const int* in_sizes, int n_in,
                              void* d_out, int out_size) {
    const float* pred = nullptr;
    const float* tbox = nullptr;
    const float* tcls = nullptr;
    const void*  mask = nullptr;
    // identify inputs by element count (robust to metadata ordering)
    for (int i = 0; i < n_in; i++) {
        switch (in_sizes[i]) {
            case 24084480: pred = (const float*)d_in[i]; break;  // NCELLS*30
            case 16056320: tcls = (const float*)d_in[i]; break;  // NCELLS*20
            case 3211264:  tbox = (const float*)d_in[i]; break;  // NCELLS*4
            case 802816:   mask = d_in[i];               break;  // NCELLS
        }
    }
    yolo_init_detect_k<<<1, 256>>>((const unsigned int*)mask);
    yolo_main_k<<<NBLOCKS, 256>>>(pred, tbox, tcls, mask, (float*)d_out);
}

// round 3
// speedup vs baseline: 1.6864x; 1.0702x over previous
#include <cuda_runtime.h>
#include <cuda_bf16.h>

// ---------------------------------------------------------------------------
// YOLO loss reduction: 1024 x 28 x 28 cells, B=2 boxes, 20 classes -> 5 scalars
// (total, reg_l, cobj_l, nbj_l, cls_l)
// SINGLE launch: per-block mask-dtype detection, last-block finalize,
// self-resetting accumulators (deterministic across graph replays).
// ---------------------------------------------------------------------------

#define NCELLS   802816      // 1024*28*28
#define NBLOCKS  3136        // NCELLS / 256
#define INV_S    0.0357142857142857f   // 1/28
#define N_BATCH  1024.0

__device__ double       g_acc[4];   // cls, nbj, reg, cobj raw sums (zero-init)
__device__ unsigned int g_count;    // finished-block ticket (zero-init)

__global__ void __launch_bounds__(256) yolo_main_k(
    const float* __restrict__ pred,   // [NCELLS, 30]
    const float* __restrict__ tbox,   // [NCELLS, 4]
    const float* __restrict__ tcls,   // [NCELLS, 20]
    const void*  __restrict__ maskp,  // [NCELLS] (dtype auto-detected)
    float*       __restrict__ out)
{
    __shared__ __align__(16) float sp[256 * 30];   // staged pred tile
    __shared__ float smk[256];                     // mask as float
    __shared__ float red[8][4];

    const int tid   = threadIdx.x;
    const int cell0 = blockIdx.x * 256;

    // --- (1) mask dtype probe: first 64 words of the buffer (L2 broadcast) --
    // word == 0x3f800000 -> float32 storage; word > 1 with all bytes in {0,1}
    // -> byte-packed bool/uint8; else int32.
    int dbits = 0;
    if (tid < 64) {
        unsigned int w = ((const unsigned int*)maskp)[tid];
        dbits  = (w == 0x3f800000u) ? 1 : 0;
        dbits |= ((w > 1u) && ((w & 0xFEFEFEFEu) == 0u)) ? 2 : 0;
    }

    // --- (2) pred staging: coalesced float4 LDG -> STS (1920 float4) -------
    {
        const float4* p4  = (const float4*)(pred + (size_t)cell0 * 30);
        float4*       sp4 = (float4*)sp;
        #pragma unroll
        for (int i = tid; i < 1920; i += 256) sp4[i] = p4[i];
    }

    // --- (3) tcls prefetch into registers (issued before any barrier) ------
    float4 tc[5];
    {
        const float4* tcg4 = (const float4*)(tcls + (size_t)cell0 * 20);
        #pragma unroll
        for (int j = 0; j < 5; j++) tc[j] = tcg4[tid + 256 * j];
    }

    // --- (4) target box: direct coalesced float4 ---------------------------
    const float4 tbv = ((const float4*)(tbox))[cell0 + tid];

    // --- (5) barrier #1: combine dtype probe (also orders nothing else yet) -
    unsigned int flag = (unsigned int)__syncthreads_or(dbits);

    // --- (6) mask load with detected dtype ---------------------------------
    {
        float mv;
        if (flag & 1u)      mv = ((const float*)maskp)[cell0 + tid];
        else if (flag & 2u) mv = (float)((const unsigned char*)maskp)[cell0 + tid];
        else                mv = (float)((const int*)maskp)[cell0 + tid];
        smk[tid] = mv;
    }
    __syncthreads();   // sp + smk visible

    // --- (7) class loss: registers (tc) vs shared pred ----------------------
    // e4 in [0,1280): cl = e4/5, ch = 4*(e4%5); float4 never crosses a cell.
    float acc_cls = 0.0f;
    #pragma unroll
    for (int j = 0; j < 5; j++) {
        int e4 = tid + 256 * j;
        int cl = e4 / 5;
        int ch = 4 * (e4 - cl * 5);
        const float* pc = sp + cl * 30 + 10 + ch;
        float mm = smk[cl];
        float d0 = pc[0] - tc[j].x;
        float d1 = pc[1] - tc[j].y;
        float d2 = pc[2] - tc[j].z;
        float d3 = pc[3] - tc[j].w;
        acc_cls += mm * (d0 * d0 + d1 * d1 + d2 * d2 + d3 * d3);
    }

    // --- (8) per-cell box terms ---------------------------------------------
    const float* p = sp + tid * 30;
    const float  m = smk[tid];

    float tcx = tbv.x * INV_S, tcy = tbv.y * INV_S;
    float thw = 0.5f * tbv.z, thh = 0.5f * tbv.w;
    float tbx1 = tcx - thw, tby1 = tcy - thh, tbx2 = tcx + thw, tby2 = tcy + thh;
    float ta = (tbx2 - tbx1) * (tby2 - tby1);

    float bx1[2], by1[2], bx2[2], by2[2], iou[2], cf[2];
    #pragma unroll
    for (int b = 0; b < 2; b++) {
        float x = p[5 * b + 0], y = p[5 * b + 1];
        float w = p[5 * b + 2], h = p[5 * b + 3];
        cf[b] = p[5 * b + 4];
        float cx = x * INV_S, cy = y * INV_S;
        float hw = 0.5f * w, hh = 0.5f * h;
        bx1[b] = cx - hw; by1[b] = cy - hh;
        bx2[b] = cx + hw; by2[b] = cy + hh;
        float ltx = fmaxf(bx1[b], tbx1), lty = fmaxf(by1[b], tby1);
        float rbx = fminf(bx2[b], tbx2), rby = fminf(by2[b], tby2);
        float wi = fmaxf(rbx - ltx, 0.0f), hi = fmaxf(rby - lty, 0.0f);
        float inter = wi * hi;
        float a1 = (bx2[b] - bx1[b]) * (by2[b] - by1[b]);
        iou[b] = inter / (a1 + ta - inter);
    }

    // argmax (first max wins on tie, matching jnp.argmax)
    int best = (iou[1] > iou[0]) ? 1 : 0;
    float biou = iou[best];
    float bbx1 = bx1[best], bby1 = by1[best], bbx2 = bx2[best], bby2 = by2[best];
    float bconf = cf[best];
    if (!(biou > 0.0f)) {
        bbx1 = bby1 = bbx2 = bby2 = 0.0f;
        bconf = 0.0f; biou = 0.0f;
    }

    float dx = bbx1 - tbx1, dy = bby1 - tby1;
    float lxy = dx * dx + dy * dy;
    float s1 = (bbx2 > 0.0f) ? sqrtf(bbx2) : 0.0f;
    float s2 = (bby2 > 0.0f) ? sqrtf(bby2) : 0.0f;
    float t1 = (tbx2 > 0.0f) ? sqrtf(tbx2) : 0.0f;
    float t2 = (tby2 > 0.0f) ? sqrtf(tby2) : 0.0f;
    float dw = s1 - t1, dh = s2 - t2;
    float lwh = dw * dw + dh * dh;

    float acc_reg  = m * (lxy + lwh);
    float dc       = bconf - biou;
    float acc_cobj = m * dc * dc;
    float acc_nbj  = (1.0f - m) * (cf[0] * cf[0] + cf[1] * cf[1]);

    // --- (9) reduction: warp shuffle -> shared -> double atomics ------------
    float a4[4] = { acc_cls, acc_nbj, acc_reg, acc_cobj };
    #pragma unroll
    for (int j = 0; j < 4; j++) {
        #pragma unroll
        for (int o = 16; o; o >>= 1)
            a4[j] += __shfl_down_sync(0xffffffffu, a4[j], o);
    }
    int warp = tid >> 5, lane = tid & 31;
    if (lane == 0) {
        red[warp][0] = a4[0]; red[warp][1] = a4[1];
        red[warp][2] = a4[2]; red[warp][3] = a4[3];
    }
    __syncthreads();
    if (tid == 0) {
        double s[4] = {0.0, 0.0, 0.0, 0.0};
        #pragma unroll
        for (int w = 0; w < 8; w++)
            for (int j = 0; j < 4; j++) s[j] += (double)red[w][j];
        atomicAdd(&g_acc[0], s[0]);
        atomicAdd(&g_acc[1], s[1]);
        atomicAdd(&g_acc[2], s[2]);
        atomicAdd(&g_acc[3], s[3]);

        __threadfence();
        unsigned int ticket = atomicAdd(&g_count, 1u);
        if (ticket == NBLOCKS - 1) {
            // all blocks' atomics to g_acc precede their g_count increment;
            // atomic reads below observe the complete sums.
            double cls  = atomicAdd(&g_acc[0], 0.0);
            double nbj  = atomicAdd(&g_acc[1], 0.0);
            double reg  = atomicAdd(&g_acc[2], 0.0);
            double cobj = atomicAdd(&g_acc[3], 0.0);
            double cls_l  = 2.0 * cls / N_BATCH;
            double nbj_l  = 0.5 * nbj / N_BATCH;
            double reg_l  = 5.0 * reg / N_BATCH;
            double cobj_l = cobj / N_BATCH;
            out[0] = (float)(cls_l + nbj_l + reg_l + cobj_l);
            out[1] = (float)reg_l;
            out[2] = (float)cobj_l;
            out[3] = (float)nbj_l;
            out[4] = (float)cls_l;
            // self-reset so the next graph replay starts clean
            atomicExch((unsigned long long*)&g_acc[0], 0ull);
            atomicExch((unsigned long long*)&g_acc[1], 0ull);
            atomicExch((unsigned long long*)&g_acc[2], 0ull);
            atomicExch((unsigned long long*)&g_acc[3], 0ull);
            atomicExch(&g_count, 0u);
        }
    }
}

extern "C" void kernel_launch(void* const* d_in, const int* in_sizes, int n_in,
                              void* d_out, int out_size) {
    const float* pred = nullptr;
    const float* tbox = nullptr;
    const float* tcls = nullptr;
    const void*  mask = nullptr;
    // identify inputs by element count (robust to metadata ordering)
    for (int i = 0; i < n_in; i++) {
        switch (in_sizes[i]) {
            case 24084480: pred = (const float*)d_in[i]; break;  // NCELLS*30
            case 16056320: tcls = (const float*)d_in[i]; break;  // NCELLS*20
            case 3211264:  tbox = (const float*)d_in[i]; break;  // NCELLS*4
            case 802816:   mask = d_in[i];               break;  // NCELLS
        }
    }
    yolo_main_k<<<NBLOCKS, 256>>>(pred, tbox, tcls, mask, (float*)d_out);
}

// round 5
// speedup vs baseline: 1.6963x; 1.0059x over previous
#include <cuda_runtime.h>
#include <cuda_bf16.h>

// ---------------------------------------------------------------------------
// YOLO loss reduction: 1024 x 28 x 28 cells, B=2 boxes, 20 classes -> 5 scalars
// Persistent double-buffered cp.async pipeline: 448 blocks x 7 tiles of 256
// cells.  Pred streams gmem->smem via cp.async.cg; tcls/tbox/mask prefetch
// into registers one tile ahead.  Single launch, last-block finalize,
// self-resetting accumulators (graph-replay deterministic).
// ---------------------------------------------------------------------------

#define NTILES   3136        // 802816 / 256
#define GRID     448         // 3136 / 448 = 7 tiles per block, exact
#define TPB      256
#define TILE_F4  1920        // 256 cells * 30 ch / 4
#define INV_S    0.0357142857142857f   // 1/28
#define N_BATCH  1024.0

__device__ double       g_acc[4];   // cls, nbj, reg, cobj raw sums (zero-init)
__device__ unsigned int g_count;    // finished-block ticket (zero-init)

__device__ __forceinline__ void cp_async16(unsigned int smem_addr, const void* gptr) {
    asm volatile("cp.async.cg.shared.global [%0], [%1], 16;\n"
                 :: "r"(smem_addr), "l"(gptr));
}
__device__ __forceinline__ void cp_async_commit() {
    asm volatile("cp.async.commit_group;\n" ::: "memory");
}
__device__ __forceinline__ void cp_async_wait1() {
    asm volatile("cp.async.wait_group 1;\n" ::: "memory");
}

__global__ void __launch_bounds__(TPB) yolo_main_k(
    const float* __restrict__ pred,   // [802816, 30]
    const float* __restrict__ tbox,   // [802816, 4]
    const float* __restrict__ tcls,   // [802816, 20]
    const unsigned int* __restrict__ mask,  // [802816] words, truth <=> w != 0
    float*       __restrict__ out)
{
    __shared__ __align__(16) float sp[2][TILE_F4 * 4];  // double-buffered pred
    __shared__ float smk[2][TPB];                        // mask as float
    __shared__ float red[8][4];

    const int tid = threadIdx.x;

    // per-thread accumulators carried across all 7 tiles
    float acc_cls = 0.0f, acc_nbj = 0.0f, acc_reg = 0.0f, acc_cobj = 0.0f;

    // ---- prologue: issue tile 0 ----
    int t0 = blockIdx.x;
    {
        const float4* p4 = (const float4*)(pred + (size_t)t0 * TPB * 30);
        unsigned int dst = (unsigned int)__cvta_generic_to_shared(&sp[0][0]);
        #pragma unroll
        for (int i = tid; i < TILE_F4; i += TPB)
            cp_async16(dst + i * 16, p4 + i);
    }
    cp_async_commit();

    float4 tcA[5]; float4 tbA; unsigned int mkA;
    {
        const float4* tcg4 = (const float4*)(tcls + (size_t)t0 * TPB * 20);
        #pragma unroll
        for (int j = 0; j < 5; j++) tcA[j] = tcg4[tid + TPB * j];
        tbA = ((const float4*)tbox)[t0 * TPB + tid];
        mkA = mask[t0 * TPB + tid];
    }

    int cur = 0;
    for (int t = t0; t < NTILES; t += GRID, cur ^= 1) {
        const int tn = t + GRID;

        // ---- issue next tile's pred into the other buffer ----
        if (tn < NTILES) {
            const float4* p4 = (const float4*)(pred + (size_t)tn * TPB * 30);
            unsigned int dst = (unsigned int)__cvta_generic_to_shared(&sp[cur ^ 1][0]);
            #pragma unroll
            for (int i = tid; i < TILE_F4; i += TPB)
                cp_async16(dst + i * 16, p4 + i);
        }
        cp_async_commit();   // group for tn (possibly empty -> completes instantly)

        // ---- register prefetch for next tile ----
        float4 tcN[5]; float4 tbN; unsigned int mkN = 0;
        if (tn < NTILES) {
            const float4* tcg4 = (const float4*)(tcls + (size_t)tn * TPB * 20);
            #pragma unroll
            for (int j = 0; j < 5; j++) tcN[j] = tcg4[tid + TPB * j];
            tbN = ((const float4*)tbox)[tn * TPB + tid];
            mkN = mask[tn * TPB + tid];
        }

        // ---- publish this tile's mask, wait for its pred, sync ----
        smk[cur][tid] = (mkA != 0u) ? 1.0f : 0.0f;
        cp_async_wait1();    // tile t's group resident (only tn's may remain)
        __syncthreads();

        // ================= compute tile t =================
        const float* spc = sp[cur];
        const float* mkc = smk[cur];

        // class loss: registers (tcA) vs shared pred
        // e4 in [0,1280): cl = e4/5, ch = 4*(e4%5); float4 never crosses a cell
        #pragma unroll
        for (int j = 0; j < 5; j++) {
            int e4 = tid + TPB * j;
            int cl = e4 / 5;
            int ch = 4 * (e4 - cl * 5);
            const float* pc = spc + cl * 30 + 10 + ch;
            float mm = mkc[cl];
            float d0 = pc[0] - tcA[j].x;
            float d1 = pc[1] - tcA[j].y;
            float d2 = pc[2] - tcA[j].z;
            float d3 = pc[3] - tcA[j].w;
            acc_cls += mm * (d0 * d0 + d1 * d1 + d2 * d2 + d3 * d3);
        }

        // per-cell box terms
        {
            const float* p = spc + tid * 30;
            const float  m = mkc[tid];

            float tcx = tbA.x * INV_S, tcy = tbA.y * INV_S;
            float thw = 0.5f * tbA.z, thh = 0.5f * tbA.w;
            float tbx1 = tcx - thw, tby1 = tcy - thh;
            float tbx2 = tcx + thw, tby2 = tcy + thh;
            float ta = (tbx2 - tbx1) * (tby2 - tby1);

            float bx1[2], by1[2], bx2[2], by2[2], iou[2], cf[2];
            #pragma unroll
            for (int b = 0; b < 2; b++) {
                float x = p[5 * b + 0], y = p[5 * b + 1];
                float w = p[5 * b + 2], h = p[5 * b + 3];
                cf[b] = p[5 * b + 4];
                float cx = x * INV_S, cy = y * INV_S;
                float hw = 0.5f * w, hh = 0.5f * h;
                bx1[b] = cx - hw; by1[b] = cy - hh;
                bx2[b] = cx + hw; by2[b] = cy + hh;
                float ltx = fmaxf(bx1[b], tbx1), lty = fmaxf(by1[b], tby1);
                float rbx = fminf(bx2[b], tbx2), rby = fminf(by2[b], tby2);
                float wi = fmaxf(rbx - ltx, 0.0f), hi = fmaxf(rby - lty, 0.0f);
                float inter = wi * hi;
                float a1 = (bx2[b] - bx1[b]) * (by2[b] - by1[b]);
                iou[b] = inter / (a1 + ta - inter);
            }

            int best = (iou[1] > iou[0]) ? 1 : 0;   // first max wins (jnp.argmax)
            float biou = iou[best];
            float bbx1 = bx1[best], bby1 = by1[best];
            float bbx2 = bx2[best], bby2 = by2[best];
            float bconf = cf[best];
            if (!(biou > 0.0f)) {
                bbx1 = bby1 = bbx2 = bby2 = 0.0f;
                bconf = 0.0f; biou = 0.0f;
            }

            float dx = bbx1 - tbx1, dy = bby1 - tby1;
            float lxy = dx * dx + dy * dy;
            float s1 = (bbx2 > 0.0f) ? sqrtf(bbx2) : 0.0f;
            float s2 = (bby2 > 0.0f) ? sqrtf(bby2) : 0.0f;
            float t1 = (tbx2 > 0.0f) ? sqrtf(tbx2) : 0.0f;
            float t2 = (tby2 > 0.0f) ? sqrtf(tby2) : 0.0f;
            float dw = s1 - t1, dh = s2 - t2;
            float lwh = dw * dw + dh * dh;

            acc_reg  += m * (lxy + lwh);
            float dc  = bconf - biou;
            acc_cobj += m * dc * dc;
            acc_nbj  += (1.0f - m) * (cf[0] * cf[0] + cf[1] * cf[1]);
        }
        __syncthreads();   // all reads of sp[cur]/smk[cur] done before reuse

        // rotate prefetched registers
        #pragma unroll
        for (int j = 0; j < 5; j++) tcA[j] = tcN[j];
        tbA = tbN; mkA = mkN;
    }

    // ---- once per block: warp shuffle -> shared -> double atomics ----
    float a4[4] = { acc_cls, acc_nbj, acc_reg, acc_cobj };
    #pragma unroll
    for (int j = 0; j < 4; j++) {
        #pragma unroll
        for (int o = 16; o; o >>= 1)
            a4[j] += __shfl_down_sync(0xffffffffu, a4[j], o);
    }
    int warp = tid >> 5, lane = tid & 31;
    if (lane == 0) {
        red[warp][0] = a4[0]; red[warp][1] = a4[1];
        red[warp][2] = a4[2]; red[warp][3] = a4[3];
    }
    __syncthreads();
    if (tid == 0) {
        double s[4] = {0.0, 0.0, 0.0, 0.0};
        #pragma unroll
        for (int w = 0; w < 8; w++)
            for (int j = 0; j < 4; j++) s[j] += (double)red[w][j];
        atomicAdd(&g_acc[0], s[0]);
        atomicAdd(&g_acc[1], s[1]);
        atomicAdd(&g_acc[2], s[2]);
        atomicAdd(&g_acc[3], s[3]);

        __threadfence();
        unsigned int ticket = atomicAdd(&g_count, 1u);
        if (ticket == GRID - 1) {
            double cls  = atomicAdd(&g_acc[0], 0.0);
            double nbj  = atomicAdd(&g_acc[1], 0.0);
            double reg  = atomicAdd(&g_acc[2], 0.0);
            double cobj = atomicAdd(&g_acc[3], 0.0);
            double cls_l  = 2.0 * cls / N_BATCH;
            double nbj_l  = 0.5 * nbj / N_BATCH;
            double reg_l  = 5.0 * reg / N_BATCH;
            double cobj_l = cobj / N_BATCH;
            out[0] = (float)(cls_l + nbj_l + reg_l + cobj_l);
            out[1] = (float)reg_l;
            out[2] = (float)cobj_l;
            out[3] = (float)nbj_l;
            out[4] = (float)cls_l;
            // self-reset for the next graph replay
            atomicExch((unsigned long long*)&g_acc[0], 0ull);
            atomicExch((unsigned long long*)&g_acc[1], 0ull);
            atomicExch((unsigned long long*)&g_acc[2], 0ull);
            atomicExch((unsigned long long*)&g_acc[3], 0ull);
            atomicExch(&g_count, 0u);
        }
    }
}

extern "C" void kernel_launch(void* const* d_in, const int* in_sizes, int n_in,
                              void* d_out, int out_size) {
    const float* pred = nullptr;
    const float* tbox = nullptr;
    const float* tcls = nullptr;
    const void*  mask = nullptr;
    for (int i = 0; i < n_in; i++) {
        switch (in_sizes[i]) {
            case 24084480: pred = (const float*)d_in[i]; break;  // 802816*30
            case 16056320: tcls = (const float*)d_in[i]; break;  // 802816*20
            case 3211264:  tbox = (const float*)d_in[i]; break;  // 802816*4
            case 802816:   mask = d_in[i];               break;  // 802816
        }
    }
    yolo_main_k<<<GRID, TPB>>>(pred, tbox, tcls,
                               (const unsigned int*)mask, (float*)d_out);
}